// round 1
// baseline (speedup 1.0000x reference)
#include <cuda_runtime.h>
#include <float.h>
#include <math.h>

#define NPTS 8192
#define CDIM 128
#define KNN  16
#define CS   16            // C / S
#define BN_INV 0.99999500003749973f   // 1/sqrt(1 + 1e-5)

// ---------------- scratch (static device globals; no allocation) ----------------
static __device__ float4 g_p4[NPTS];
static __device__ int    g_idx[NPTS * KNN];
static __device__ float  g_d2 [NPTS * KNN];
static __device__ float  g_xq [NPTS * CDIM];
static __device__ float  g_xk [NPTS * CDIM];
static __device__ float  g_xv [NPTS * CDIM];

// ---------------- kernel 0: pack p into float4 (x,y,z,|p|^2) ----------------
__global__ void prep_kernel(const float* __restrict__ p) {
    int i = blockIdx.x * blockDim.x + threadIdx.x;
    if (i < NPTS) {
        float x = p[i * 3 + 0], y = p[i * 3 + 1], z = p[i * 3 + 2];
        g_p4[i] = make_float4(x, y, z, x * x + y * y + z * z);
    }
}

// ---------------- kernel 1: KNN, one query per block ----------------
// d2 array in smem; 16 rounds of block argmin with lazy per-thread local minima.
__global__ __launch_bounds__(256, 4) void knn_kernel() {
    __shared__ float sd[NPTS];
    __shared__ float lm[256];
    __shared__ int   li[256];
    __shared__ float wm[8];
    __shared__ int   wi[8];
    __shared__ int   s_owner;

    const int n = blockIdx.x;
    const int t = threadIdx.x;

    const float4 q = g_p4[n];

    float bv = FLT_MAX; int bi = -1;
    #pragma unroll 4
    for (int j = t; j < NPTS; j += 256) {
        float4 pj = g_p4[j];
        // EXACT reference formula: sq_i + sq_j - 2*dot  (keeps the selected set identical)
        float d2 = q.w + pj.w - 2.0f * (q.x * pj.x + q.y * pj.y + q.z * pj.z);
        sd[j] = d2;
        if (d2 < bv || (d2 == bv && j < bi)) { bv = d2; bi = j; }
    }
    lm[t] = bv; li[t] = bi;
    __syncthreads();

    const int lane = t & 31, w = t >> 5;
    for (int r = 0; r < KNN; ++r) {
        // reduce 256 cached local minima
        float v = lm[t]; int vi = li[t];
        #pragma unroll
        for (int s = 16; s > 0; s >>= 1) {
            float ov = __shfl_down_sync(0xffffffffu, v, s);
            int   oi = __shfl_down_sync(0xffffffffu, vi, s);
            if (ov < v || (ov == v && oi < vi)) { v = ov; vi = oi; }
        }
        if (lane == 0) { wm[w] = v; wi[w] = vi; }
        __syncthreads();
        if (t == 0) {
            float fv = wm[0]; int fi = wi[0];
            #pragma unroll
            for (int w2 = 1; w2 < 8; ++w2)
                if (wm[w2] < fv || (wm[w2] == fv && wi[w2] < fi)) { fv = wm[w2]; fi = wi[w2]; }
            g_idx[n * KNN + r] = fi;
            g_d2 [n * KNN + r] = fv;
            sd[fi] = FLT_MAX;            // remove winner
            s_owner = fi & 255;          // its owning thread must rescan
        }
        __syncthreads();
        if (t == s_owner) {
            float nb = FLT_MAX; int ni = -1;
            #pragma unroll 4
            for (int j = t; j < NPTS; j += 256) {
                float d = sd[j];
                if (d < nb || (d == nb && j < ni)) { nb = d; ni = j; }
            }
            lm[t] = nb; li[t] = ni;
        }
        __syncthreads();
    }
}

// ---------------- kernel 2: three 8192x128x128 fp32 GEMMs (xq,xk,xv) ----------------
// blockIdx.y selects which weight; BM=64, BN=128(full), BK=16, 256 threads, 4x8 per thread
__global__ __launch_bounds__(256, 2) void gemm3_kernel(
    const float* __restrict__ x,
    const float* __restrict__ Wq, const float* __restrict__ bq,
    const float* __restrict__ Wk, const float* __restrict__ bk,
    const float* __restrict__ Wv, const float* __restrict__ bv)
{
    __shared__ float  As[64][17];
    __shared__ float4 Bs[16][32];   // 16 x 128 floats

    const float* W; const float* b; float* out;
    if (blockIdx.y == 0)      { W = Wq; b = bq; out = g_xq; }
    else if (blockIdx.y == 1) { W = Wk; b = bk; out = g_xk; }
    else                      { W = Wv; b = bv; out = g_xv; }

    const int t  = threadIdx.x;
    const int tx = t & 15, ty = t >> 4;
    const int row0 = blockIdx.x * 64;

    float acc[4][8];
    #pragma unroll
    for (int i = 0; i < 4; ++i)
        #pragma unroll
        for (int j = 0; j < 8; ++j) acc[i][j] = 0.0f;

    for (int k0 = 0; k0 < CDIM; k0 += 16) {
        #pragma unroll
        for (int i = 0; i < 4; ++i) {
            int lin = t + i * 256;
            int r = lin >> 4, kk = lin & 15;
            As[r][kk] = x[(row0 + r) * CDIM + k0 + kk];
        }
        #pragma unroll
        for (int i = 0; i < 8; ++i) {
            int lin = t + i * 256;
            int kk = lin >> 7, col = lin & 127;
            ((float*)Bs)[kk * 128 + col] = W[(k0 + kk) * CDIM + col];
        }
        __syncthreads();
        #pragma unroll
        for (int kk = 0; kk < 16; ++kk) {
            float a[4];
            #pragma unroll
            for (int i = 0; i < 4; ++i) a[i] = As[ty * 4 + i][kk];
            float4 b0 = Bs[kk][tx * 2 + 0];
            float4 b1 = Bs[kk][tx * 2 + 1];
            float bb[8] = {b0.x, b0.y, b0.z, b0.w, b1.x, b1.y, b1.z, b1.w};
            #pragma unroll
            for (int i = 0; i < 4; ++i)
                #pragma unroll
                for (int j = 0; j < 8; ++j)
                    acc[i][j] = fmaf(a[i], bb[j], acc[i][j]);
        }
        __syncthreads();
    }
    #pragma unroll
    for (int i = 0; i < 4; ++i) {
        int r = row0 + ty * 4 + i;
        #pragma unroll
        for (int j = 0; j < 8; ++j) {
            int c = tx * 8 + j;
            out[r * CDIM + c] = acc[i][j] + __ldg(&b[c]);
        }
    }
}

// ---------------- kernel 3: fused attention tail, one query per block ----------------
#define PITCH 136   // 136*4 = 544 bytes, 16B aligned, breaks bank-conflict patterns
__global__ __launch_bounds__(256, 4) void attn_kernel(
    float* __restrict__ outp,
    const float* __restrict__ Wp1, const float* __restrict__ bp1,
    const float* __restrict__ g1,  const float* __restrict__ be1,
    const float* __restrict__ Wp2, const float* __restrict__ bp2,
    const float* __restrict__ g2,  const float* __restrict__ be2,
    const float* __restrict__ Ww1, const float* __restrict__ bw1,
    const float* __restrict__ g3,  const float* __restrict__ be3,
    const float* __restrict__ Ww2, const float* __restrict__ bw2)
{
    __shared__ float s_pr [KNN][PITCH];
    __shared__ float s_w0 [KNN][PITCH];
    __shared__ float s_xv [KNN][PITCH];
    __shared__ float s_w1t[CS][PITCH];     // Ww1 transposed: [j][c]
    __shared__ float s_ww2[CS][CS];
    __shared__ float s_pr1[KNN][4];
    __shared__ float s_dw [KNN];
    __shared__ int   s_id [KNN];
    __shared__ float s_mat[KNN][17];
    __shared__ float s_w2 [KNN][17];

    const int n = blockIdx.x;
    const int t = threadIdx.x;

    // load Ww1 transposed + Ww2 into smem
    for (int i = t; i < CDIM * CS; i += 256) {
        int c = i >> 4, j = i & 15;
        s_w1t[j][c] = Ww1[i];
    }
    if (t < 256) { /* 256 == CS*CS */ s_ww2[t >> 4][t & 15] = Ww2[t]; }

    // phase A: per-neighbor scalars: idx, dist weight, linear_p stage-1 (3->3, bn, relu)
    if (t < KNN) {
        int id = g_idx[n * KNN + t];
        s_id[t] = id;
        float d2 = g_d2[n * KNN + t];
        s_dw[t] = expf(-sqrtf(fmaxf(d2, 0.0f)));
        float4 pq = g_p4[n], pj = g_p4[id];
        float rx = pj.x - pq.x, ry = pj.y - pq.y, rz = pj.z - pq.z;
        #pragma unroll
        for (int j = 0; j < 3; ++j) {
            float v = rx * Wp1[0 * 3 + j] + ry * Wp1[1 * 3 + j] + rz * Wp1[2 * 3 + j] + bp1[j];
            v = v * (g1[j] * BN_INV) + be1[j];
            s_pr1[t][j] = fmaxf(v, 0.0f);
        }
    }
    __syncthreads();

    // phase A2: pr (3->C), gather xk/xv, w0 = relu(bn2(xq - xk + pr))
    {
        const int half = t >> 7;          // 0/1
        const int c    = t & 127;
        const float xqc  = g_xq[n * CDIM + c];
        const float wp0  = Wp2[0 * CDIM + c];
        const float wp1c = Wp2[1 * CDIM + c];
        const float wp2c = Wp2[2 * CDIM + c];
        const float bpc  = bp2[c];
        const float sc2  = g2[c] * BN_INV;
        const float bec  = be2[c];
        #pragma unroll
        for (int kk = 0; kk < 8; ++kk) {
            int k  = half * 8 + kk;
            int id = s_id[k];
            float prv = s_pr1[k][0] * wp0 + s_pr1[k][1] * wp1c + s_pr1[k][2] * wp2c + bpc;
            s_pr[k][c] = prv;
            float w0 = xqc - __ldg(&g_xk[id * CDIM + c]) + prv;
            w0 = fmaxf(w0 * sc2 + bec, 0.0f);
            s_w0[k][c] = w0;
            s_xv[k][c] = __ldg(&g_xv[id * CDIM + c]);
        }
    }
    __syncthreads();

    // phase B: w1 = w0 @ Ww1 (128 -> 16), bn3+relu, then w2 = h @ Ww2 (16 -> 16)
    const int k = t >> 4, j = t & 15;
    {
        float acc = bw1[j];
        const float4* w0r = (const float4*)&s_w0[k][0];
        const float4* wtr = (const float4*)&s_w1t[j][0];
        #pragma unroll
        for (int c4 = 0; c4 < 32; ++c4) {
            float4 a = w0r[c4], wv = wtr[c4];
            acc += a.x * wv.x + a.y * wv.y + a.z * wv.z + a.w * wv.w;
        }
        float h = fmaxf(acc * (g3[j] * BN_INV) + be3[j], 0.0f);
        s_mat[k][j] = h;
    }
    __syncthreads();
    {
        float acc2 = bw2[j];
        #pragma unroll
        for (int j2 = 0; j2 < CS; ++j2)
            acc2 += s_mat[k][j2] * s_ww2[j2][j];
        s_w2[k][j] = acc2;
    }
    __syncthreads();

    // phase C: softmax over k (axis=1) per channel j
    {
        float m = -FLT_MAX;
        #pragma unroll
        for (int k2 = 0; k2 < KNN; ++k2) m = fmaxf(m, s_w2[k2][j]);
        float e = expf(s_w2[k][j] - m);
        s_mat[k][j] = e;
    }
    __syncthreads();
    {
        float ssum = 0.0f;
        #pragma unroll
        for (int k2 = 0; k2 < KNN; ++k2) ssum += s_mat[k2][j];
        s_w2[k][j] = s_mat[k][j] / ssum;
    }
    __syncthreads();

    // phase D: out[c] = sum_k (xv*dw + pr) * w[k][c%16]
    if (t < CDIM) {
        const int c = t, jj = t & 15;
        float o = 0.0f;
        #pragma unroll
        for (int k2 = 0; k2 < KNN; ++k2)
            o = fmaf(fmaf(s_xv[k2][c], s_dw[k2], s_pr[k2][c]), s_w2[k2][jj], o);
        outp[n * CDIM + c] = o;
    }
}

// ---------------- launch ----------------
extern "C" void kernel_launch(void* const* d_in, const int* in_sizes, int n_in,
                              void* d_out, int out_size) {
    const float* p   = (const float*)d_in[0];
    const float* x   = (const float*)d_in[1];
    const float* Wq  = (const float*)d_in[2];
    const float* bq  = (const float*)d_in[3];
    const float* Wk  = (const float*)d_in[4];
    const float* bk  = (const float*)d_in[5];
    const float* Wv  = (const float*)d_in[6];
    const float* bv  = (const float*)d_in[7];
    const float* Wp1 = (const float*)d_in[8];
    const float* bp1 = (const float*)d_in[9];
    const float* g1  = (const float*)d_in[10];
    const float* be1 = (const float*)d_in[11];
    const float* Wp2 = (const float*)d_in[12];
    const float* bp2 = (const float*)d_in[13];
    const float* g2  = (const float*)d_in[14];
    const float* be2 = (const float*)d_in[15];
    const float* Ww1 = (const float*)d_in[16];
    const float* bw1 = (const float*)d_in[17];
    const float* g3  = (const float*)d_in[18];
    const float* be3 = (const float*)d_in[19];
    const float* Ww2 = (const float*)d_in[20];
    const float* bw2 = (const float*)d_in[21];
    float* outp = (float*)d_out;

    prep_kernel<<<(NPTS + 255) / 256, 256>>>(p);
    gemm3_kernel<<<dim3(NPTS / 64, 3), 256>>>(x, Wq, bq, Wk, bk, Wv, bv);
    knn_kernel<<<NPTS, 256>>>();
    attn_kernel<<<NPTS, 256>>>(outp, Wp1, bp1, g1, be1, Wp2, bp2,
                               g2, be2, Ww1, bw1, g3, be3, Ww2, bw2);
}